// round 2
// baseline (speedup 1.0000x reference)
#include <cuda_runtime.h>
#include <math.h>

// Shapes (fixed by the problem)
#define B_   2
#define H_   8
#define N_   64
#define TD_  1024          // T*D = 32*32
#define BH_  (B_ * H_)     // 16
#define INV_SCALE_ (1.0f / 32.0f)   // 1/sqrt(T*D)

// Raw (pre-softmax, pre-mask) scores scratch: [BH, N, N]
__device__ float g_scores[BH_ * N_ * N_];

// ---------------------------------------------------------------------------
// Kernel A: tiled QK^T.  One block per 16x16 score tile.
// grid = BH * 16 tiles = 256 blocks, 256 threads.
// Per block: reads 16 Q rows + 16 K rows in 8 chunks of 128 floats via smem.
// ---------------------------------------------------------------------------
#define TILE_ 16
#define CHUNK_ 128
#define SSTRIDE_ 132   // floats; 132%32==4 -> conflict-free float4 reads, 16B aligned

__global__ __launch_bounds__(256, 4)
void qk_scores_kernel(const float* __restrict__ Q,
                      const float* __restrict__ K)
{
    __shared__ float sQ[TILE_ * SSTRIDE_];
    __shared__ float sK[TILE_ * SSTRIDE_];

    const int bx   = blockIdx.x;            // 0..255
    const int bh   = bx >> 4;                // /16
    const int tile = bx & 15;
    const int ti0  = (tile >> 2) * TILE_;    // i-tile origin
    const int tj0  = (tile & 3)  * TILE_;    // j-tile origin

    const int tid = threadIdx.x;
    const int ti  = tid >> 4;    // 0..15
    const int tj  = tid & 15;    // 0..15

    // loader mapping: each thread loads 8 consecutive floats of one row
    const int lr = tid >> 4;            // row 0..15
    const int ld = (tid & 15) * 8;      // col 0..120

    float acc = 0.0f;

    for (int c = 0; c < TD_ / CHUNK_; ++c) {
        const int d0 = c * CHUNK_;
        // load Q tile
        {
            const float4* src = reinterpret_cast<const float4*>(
                Q + (size_t)(bh * N_ + ti0 + lr) * TD_ + d0 + ld);
            float4 a = src[0], b = src[1];
            float4* dst = reinterpret_cast<float4*>(&sQ[lr * SSTRIDE_ + ld]);
            dst[0] = a; dst[1] = b;
        }
        // load K tile
        {
            const float4* src = reinterpret_cast<const float4*>(
                K + (size_t)(bh * N_ + tj0 + lr) * TD_ + d0 + ld);
            float4 a = src[0], b = src[1];
            float4* dst = reinterpret_cast<float4*>(&sK[lr * SSTRIDE_ + ld]);
            dst[0] = a; dst[1] = b;
        }
        __syncthreads();

        const float4* q4 = reinterpret_cast<const float4*>(&sQ[ti * SSTRIDE_]);
        const float4* k4 = reinterpret_cast<const float4*>(&sK[tj * SSTRIDE_]);
#pragma unroll
        for (int d = 0; d < CHUNK_ / 4; ++d) {
            float4 a = q4[d];
            float4 b = k4[d];
            acc += a.x * b.x + a.y * b.y + a.z * b.z + a.w * b.w;
        }
        __syncthreads();
    }

    g_scores[((size_t)bh * N_ + ti0 + ti) * N_ + tj0 + tj] = acc * INV_SCALE_;
}

// ---------------------------------------------------------------------------
// Kernel B: per-(bh,i) softmax over the score row + streaming V contraction.
// grid = BH*N = 1024 blocks, 256 threads.
// ---------------------------------------------------------------------------
__global__ __launch_bounds__(256, 4)
void attn_v_kernel(const float* __restrict__ V,
                   const int*   __restrict__ mask,
                   float*       __restrict__ out)
{
    const int bx   = blockIdx.x;          // 0 .. BH*N-1
    const int i    = bx % N_;
    const int bh   = bx / N_;
    const int tid  = threadIdx.x;
    const int lane = tid & 31;
    const int warp = tid >> 5;

    __shared__ float s_attn[N_];

    // warp 0: mask + softmax over the 64-wide score row
    if (warp == 0) {
        const size_t roff = ((size_t)bh * N_ + i) * N_;
        float v0 = g_scores[roff + lane];
        float v1 = g_scores[roff + lane + 32];
        int m0 = mask[roff + lane];
        int m1 = mask[roff + lane + 32];
        if (m0 == 0) v0 = -INFINITY;
        if (m1 == 0) v1 = -INFINITY;
        float mx = fmaxf(v0, v1);
#pragma unroll
        for (int o = 16; o > 0; o >>= 1) mx = fmaxf(mx, __shfl_xor_sync(0xffffffffu, mx, o));
        float e0 = __expf(v0 - mx);
        float e1 = __expf(v1 - mx);
        float s = e0 + e1;
#pragma unroll
        for (int o = 16; o > 0; o >>= 1) s += __shfl_xor_sync(0xffffffffu, s, o);
        float inv = 1.0f / s;
        s_attn[lane]      = e0 * inv;
        s_attn[lane + 32] = e1 * inv;
    }
    __syncthreads();

    // streaming contraction: out[tf] = sum_j attn[j] * V[bh, j, i, tf]
    const float4* Vbase = reinterpret_cast<const float4*>(V) +
                          ((size_t)bh * N_ * N_ + i) * (TD_ / 4) + tid;
    const size_t jstride = (size_t)N_ * (TD_ / 4);   // float4 stride between j's

    float4 acc = make_float4(0.f, 0.f, 0.f, 0.f);

#pragma unroll
    for (int j0 = 0; j0 < N_; j0 += 8) {
        float4 v[8];
#pragma unroll
        for (int jj = 0; jj < 8; ++jj)
            v[jj] = __ldcs(&Vbase[(size_t)(j0 + jj) * jstride]);
#pragma unroll
        for (int jj = 0; jj < 8; ++jj) {
            float a = s_attn[j0 + jj];
            acc.x += a * v[jj].x;
            acc.y += a * v[jj].y;
            acc.z += a * v[jj].z;
            acc.w += a * v[jj].w;
        }
    }

    float4* Orow = reinterpret_cast<float4*>(out + (size_t)(bh * N_ + i) * TD_);
    Orow[tid] = acc;
}

extern "C" void kernel_launch(void* const* d_in, const int* in_sizes, int n_in,
                              void* d_out, int out_size)
{
    const float* Q    = (const float*)d_in[0];
    const float* K    = (const float*)d_in[1];
    const float* V    = (const float*)d_in[2];
    const int*   mask = (const int*)d_in[3];
    float*       out  = (float*)d_out;

    qk_scores_kernel<<<BH_ * 16, 256>>>(Q, K);
    attn_v_kernel<<<BH_ * N_, 256>>>(V, mask, out);
}

// round 3
// speedup vs baseline: 1.1870x; 1.1870x over previous
#include <cuda_runtime.h>
#include <math.h>

// Shapes (fixed by the problem)
#define B_   2
#define H_   8
#define N_   64
#define TD_  1024          // T*D = 32*32
#define BH_  (B_ * H_)     // 16
#define INV_SCALE_ (1.0f / 32.0f)   // 1/sqrt(T*D)

#define KCH_  64                 // k-elements per chunk
#define NCH_  (TD_ / KCH_)       // 16 chunks
#define SSTR_ 65                 // smem row stride (odd -> conflict-free)

// Partial scores: [chunk][bh][(m*4+n)*256 + tid]  where
// score(row = ty+16m, col = tx+16n), tid = tx*16+ty.   16*16*4096 floats = 4 MB
__device__ float g_part[NCH_ * BH_ * N_ * N_];

// ---------------------------------------------------------------------------
// Kernel A: partial QK^T. grid = NCH_*BH_ = 256 blocks, 256 threads.
// Each block: full 64x64 score tile for one (bh) over one 64-wide k chunk,
// 4x4 register blocking per thread.
// ---------------------------------------------------------------------------
__global__ __launch_bounds__(256, 2)
void qk_part_kernel(const float* __restrict__ Q,
                    const float* __restrict__ K)
{
    __shared__ float sQ[N_ * SSTR_];
    __shared__ float sK[N_ * SSTR_];

    const int bx = blockIdx.x;
    const int bh = bx & (BH_ - 1);
    const int c  = bx >> 4;          // chunk index 0..15
    const int tid = threadIdx.x;

    // Fill: 4096 floats per tile, 16 per thread, coalesced.
#pragma unroll
    for (int it = 0; it < 16; ++it) {
        int idx = tid + 256 * it;
        int row = idx >> 6;          // 0..63
        int col = idx & 63;          // 0..63
        size_t g = (size_t)(bh * N_ + row) * TD_ + c * KCH_ + col;
        sQ[row * SSTR_ + col] = Q[g];
        sK[row * SSTR_ + col] = K[g];
    }
    __syncthreads();

    const int ty = tid & 15;         // row group
    const int tx = tid >> 4;         // col group

    float acc[4][4];
#pragma unroll
    for (int m = 0; m < 4; ++m)
#pragma unroll
        for (int n = 0; n < 4; ++n) acc[m][n] = 0.0f;

#pragma unroll 4
    for (int k = 0; k < KCH_; ++k) {
        float q[4], kk[4];
#pragma unroll
        for (int m = 0; m < 4; ++m) q[m]  = sQ[(ty + 16 * m) * SSTR_ + k];
#pragma unroll
        for (int n = 0; n < 4; ++n) kk[n] = sK[(tx + 16 * n) * SSTR_ + k];
#pragma unroll
        for (int m = 0; m < 4; ++m)
#pragma unroll
            for (int n = 0; n < 4; ++n)
                acc[m][n] += q[m] * kk[n];
    }

    // Coalesced store: layout [c][bh][(m*4+n)*256 + tid]
    float* dst = g_part + ((size_t)c * BH_ + bh) * (N_ * N_);
#pragma unroll
    for (int m = 0; m < 4; ++m)
#pragma unroll
        for (int n = 0; n < 4; ++n)
            dst[(m * 4 + n) * 256 + tid] = acc[m][n];
}

// ---------------------------------------------------------------------------
// Kernel B: per-(bh,i) partial-sum + mask + softmax, then streaming V pass.
// grid = BH*N = 1024 blocks, 256 threads.
// ---------------------------------------------------------------------------
__global__ __launch_bounds__(256, 4)
void attn_v_kernel(const float* __restrict__ V,
                   const int*   __restrict__ mask,
                   float*       __restrict__ out)
{
    const int bx   = blockIdx.x;          // 0 .. BH*N-1
    const int i    = bx % N_;
    const int bh   = bx / N_;
    const int tid  = threadIdx.x;
    const int lane = tid & 31;
    const int warp = tid >> 5;

    __shared__ float s_attn[N_];

    // warp 0: gather partial scores, sum, mask, softmax
    if (warp == 0) {
        const int m  = i >> 4;
        const int ty = i & 15;

        // lane handles j = lane and j = lane+32
        int j0 = lane, j1 = lane + 32;
        int idx0 = ((m * 4 + (j0 >> 4)) * 256) + ((j0 & 15) * 16 + ty);
        int idx1 = ((m * 4 + (j1 >> 4)) * 256) + ((j1 & 15) * 16 + ty);

        const float* base = g_part + (size_t)bh * (N_ * N_);
        float v0 = 0.0f, v1 = 0.0f;
#pragma unroll
        for (int cch = 0; cch < NCH_; ++cch) {
            const float* p = base + (size_t)cch * (BH_ * N_ * N_);
            v0 += p[idx0];
            v1 += p[idx1];
        }
        v0 *= INV_SCALE_;
        v1 *= INV_SCALE_;

        const size_t roff = ((size_t)bh * N_ + i) * N_;
        if (mask[roff + j0] == 0) v0 = -INFINITY;
        if (mask[roff + j1] == 0) v1 = -INFINITY;

        float mx = fmaxf(v0, v1);
#pragma unroll
        for (int o = 16; o > 0; o >>= 1) mx = fmaxf(mx, __shfl_xor_sync(0xffffffffu, mx, o));
        float e0 = __expf(v0 - mx);
        float e1 = __expf(v1 - mx);
        float s = e0 + e1;
#pragma unroll
        for (int o = 16; o > 0; o >>= 1) s += __shfl_xor_sync(0xffffffffu, s, o);
        float inv = 1.0f / s;
        s_attn[j0] = e0 * inv;
        s_attn[j1] = e1 * inv;
    }
    __syncthreads();

    // streaming contraction: out[tf] = sum_j attn[j] * V[bh, j, i, tf]
    const float4* Vbase = reinterpret_cast<const float4*>(V) +
                          ((size_t)bh * N_ * N_ + i) * (TD_ / 4) + tid;
    const size_t jstride = (size_t)N_ * (TD_ / 4);   // float4 stride between j's

    float4 acc = make_float4(0.f, 0.f, 0.f, 0.f);

#pragma unroll
    for (int j0 = 0; j0 < N_; j0 += 8) {
        float4 v[8];
#pragma unroll
        for (int jj = 0; jj < 8; ++jj)
            v[jj] = __ldcs(&Vbase[(size_t)(j0 + jj) * jstride]);
#pragma unroll
        for (int jj = 0; jj < 8; ++jj) {
            float a = s_attn[j0 + jj];
            acc.x += a * v[jj].x;
            acc.y += a * v[jj].y;
            acc.z += a * v[jj].z;
            acc.w += a * v[jj].w;
        }
    }

    float4* Orow = reinterpret_cast<float4*>(out + (size_t)(bh * N_ + i) * TD_);
    Orow[tid] = acc;
}

extern "C" void kernel_launch(void* const* d_in, const int* in_sizes, int n_in,
                              void* d_out, int out_size)
{
    const float* Q    = (const float*)d_in[0];
    const float* K    = (const float*)d_in[1];
    const float* V    = (const float*)d_in[2];
    const int*   mask = (const int*)d_in[3];
    float*       out  = (float*)d_out;

    qk_part_kernel<<<NCH_ * BH_, 256>>>(Q, K);
    attn_v_kernel<<<BH_ * N_, 256>>>(V, mask, out);
}

// round 4
// speedup vs baseline: 1.3596x; 1.1454x over previous
#include <cuda_runtime.h>
#include <math.h>

// Shapes (fixed by the problem)
#define B_   2
#define H_   8
#define N_   64
#define TD_  1024          // T*D = 32*32
#define BH_  (B_ * H_)     // 16
#define INV_SCALE_ (1.0f / 32.0f)   // 1/sqrt(T*D)

#define KCH_  64                 // k-elements per chunk
#define NCH_  (TD_ / KCH_)       // 16 chunks
#define SSTR_ 65                 // smem row stride (odd -> conflict-free)

#define PREF_J_ 16               // V rows prefetched to L2 pre-sync in kernel B

// Partial scores: [chunk][bh][(m*4+n)*256 + tid]  where
// score(row = ty+16m, col = tx+16n), tid = tx*16+ty.   16*16*4096 floats = 4 MB
__device__ float g_part[NCH_ * BH_ * N_ * N_];

// ---------------------------------------------------------------------------
// Kernel A: partial QK^T. grid = NCH_*BH_ = 256 blocks, 256 threads.
// Triggers programmatic launch of B immediately (B's pre-sync work is
// independent of A's output; B hard-syncs on grid dependency before use).
// ---------------------------------------------------------------------------
__global__ __launch_bounds__(256, 2)
void qk_part_kernel(const float* __restrict__ Q,
                    const float* __restrict__ K)
{
#if __CUDA_ARCH__ >= 900
    cudaTriggerProgrammaticLaunchCompletion();
#endif

    __shared__ float sQ[N_ * SSTR_];
    __shared__ float sK[N_ * SSTR_];

    const int bx = blockIdx.x;
    const int bh = bx & (BH_ - 1);
    const int c  = bx >> 4;          // chunk index 0..15
    const int tid = threadIdx.x;

    // Fill: 4096 floats per tile, 16 per thread, coalesced.
#pragma unroll
    for (int it = 0; it < 16; ++it) {
        int idx = tid + 256 * it;
        int row = idx >> 6;          // 0..63
        int col = idx & 63;          // 0..63
        size_t g = (size_t)(bh * N_ + row) * TD_ + c * KCH_ + col;
        sQ[row * SSTR_ + col] = Q[g];
        sK[row * SSTR_ + col] = K[g];
    }
    __syncthreads();

    const int ty = tid & 15;         // row group
    const int tx = tid >> 4;         // col group

    float acc[4][4];
#pragma unroll
    for (int m = 0; m < 4; ++m)
#pragma unroll
        for (int n = 0; n < 4; ++n) acc[m][n] = 0.0f;

#pragma unroll 4
    for (int k = 0; k < KCH_; ++k) {
        float q[4], kk[4];
#pragma unroll
        for (int m = 0; m < 4; ++m) q[m]  = sQ[(ty + 16 * m) * SSTR_ + k];
#pragma unroll
        for (int n = 0; n < 4; ++n) kk[n] = sK[(tx + 16 * n) * SSTR_ + k];
#pragma unroll
        for (int m = 0; m < 4; ++m)
#pragma unroll
            for (int n = 0; n < 4; ++n)
                acc[m][n] += q[m] * kk[n];
    }

    // Coalesced store: layout [c][bh][(m*4+n)*256 + tid]
    float* dst = g_part + ((size_t)c * BH_ + bh) * (N_ * N_);
#pragma unroll
    for (int m = 0; m < 4; ++m)
#pragma unroll
        for (int n = 0; n < 4; ++n)
            dst[(m * 4 + n) * 256 + tid] = acc[m][n];
}

// ---------------------------------------------------------------------------
// Kernel B: per-(bh,i) partial-sum + mask + softmax, then streaming V pass.
// grid = BH*N = 1024 blocks, 256 threads. Launched with PDL: prologue +
// V L2-prefetch run concurrently with kernel A.
// ---------------------------------------------------------------------------
__global__ __launch_bounds__(256, 4)
void attn_v_kernel(const float* __restrict__ V,
                   const int*   __restrict__ mask,
                   float*       __restrict__ out)
{
    const int bx   = blockIdx.x;          // 0 .. BH*N-1
    const int i    = bx % N_;
    const int bh   = bx / N_;
    const int tid  = threadIdx.x;
    const int lane = tid & 31;
    const int warp = tid >> 5;

    __shared__ float s_attn[N_];

    // ---- Pre-sync (independent of kernel A's output) ----
    const float4* Vbase = reinterpret_cast<const float4*>(V) +
                          ((size_t)bh * N_ * N_ + i) * (TD_ / 4) + tid;
    const size_t jstride = (size_t)N_ * (TD_ / 4);   // float4 stride between j's

    // Prefetch the first PREF_J_ V rows into L2 while A still runs.
#pragma unroll
    for (int j = 0; j < PREF_J_; ++j)
        asm volatile("prefetch.global.L2 [%0];" :: "l"(Vbase + (size_t)j * jstride));

    // Mask loads (input, not produced by A)
    int m0 = 1, m1 = 1;
    int idx0 = 0, idx1 = 0;
    if (warp == 0) {
        const size_t roff = ((size_t)bh * N_ + i) * N_;
        m0 = mask[roff + lane];
        m1 = mask[roff + lane + 32];
        const int m  = i >> 4;
        const int ty = i & 15;
        int j0 = lane, j1 = lane + 32;
        idx0 = ((m * 4 + (j0 >> 4)) * 256) + ((j0 & 15) * 16 + ty);
        idx1 = ((m * 4 + (j1 >> 4)) * 256) + ((j1 & 15) * 16 + ty);
    }

    // ---- Wait for kernel A's g_part to be visible ----
#if __CUDA_ARCH__ >= 900
    cudaGridDependencySynchronize();
#endif

    // warp 0: gather partial scores, sum, mask, softmax
    if (warp == 0) {
        const float* base = g_part + (size_t)bh * (N_ * N_);
        float v0 = 0.0f, v1 = 0.0f;
#pragma unroll
        for (int cch = 0; cch < NCH_; ++cch) {
            const float* p = base + (size_t)cch * (BH_ * N_ * N_);
            v0 += p[idx0];
            v1 += p[idx1];
        }
        v0 *= INV_SCALE_;
        v1 *= INV_SCALE_;

        if (m0 == 0) v0 = -INFINITY;
        if (m1 == 0) v1 = -INFINITY;

        float mx = fmaxf(v0, v1);
#pragma unroll
        for (int o = 16; o > 0; o >>= 1) mx = fmaxf(mx, __shfl_xor_sync(0xffffffffu, mx, o));
        float e0 = __expf(v0 - mx);
        float e1 = __expf(v1 - mx);
        float s = e0 + e1;
#pragma unroll
        for (int o = 16; o > 0; o >>= 1) s += __shfl_xor_sync(0xffffffffu, s, o);
        float inv = 1.0f / s;
        s_attn[lane]      = e0 * inv;
        s_attn[lane + 32] = e1 * inv;
    }
    __syncthreads();

    // streaming contraction: out[tf] = sum_j attn[j] * V[bh, j, i, tf]
    float4 acc = make_float4(0.f, 0.f, 0.f, 0.f);

#pragma unroll
    for (int j0 = 0; j0 < N_; j0 += 8) {
        float4 v[8];
#pragma unroll
        for (int jj = 0; jj < 8; ++jj)
            v[jj] = __ldcs(&Vbase[(size_t)(j0 + jj) * jstride]);
#pragma unroll
        for (int jj = 0; jj < 8; ++jj) {
            float a = s_attn[j0 + jj];
            acc.x += a * v[jj].x;
            acc.y += a * v[jj].y;
            acc.z += a * v[jj].z;
            acc.w += a * v[jj].w;
        }
    }

    float4* Orow = reinterpret_cast<float4*>(out + (size_t)(bh * N_ + i) * TD_);
    Orow[tid] = acc;
}

extern "C" void kernel_launch(void* const* d_in, const int* in_sizes, int n_in,
                              void* d_out, int out_size)
{
    const float* Q    = (const float*)d_in[0];
    const float* K    = (const float*)d_in[1];
    const float* V    = (const float*)d_in[2];
    const int*   mask = (const int*)d_in[3];
    float*       out  = (float*)d_out;

    // Kernel A: normal launch
    qk_part_kernel<<<NCH_ * BH_, 256>>>(Q, K);

    // Kernel B: programmatic dependent launch (overlaps prologue with A)
    cudaLaunchConfig_t cfg = {};
    cfg.gridDim  = dim3(BH_ * N_);
    cfg.blockDim = dim3(256);
    cfg.dynamicSmemBytes = 0;
    cudaLaunchAttribute attrs[1];
    attrs[0].id = cudaLaunchAttributeProgrammaticStreamSerialization;
    attrs[0].val.programmaticStreamSerializationAllowed = 1;
    cfg.attrs = attrs;
    cfg.numAttrs = 1;
    cudaLaunchKernelEx(&cfg, attn_v_kernel, V, mask, out);
}